// round 3
// baseline (speedup 1.0000x reference)
#include <cuda_runtime.h>
#include <math.h>

#define EPSF 1e-8f
#define RCUT 4.8f
#define NBK 64
#define NN 20
#define PI_F 3.14159265358979323846f

struct WSmem {
    float W0[15 * 64];
    float W1[64 * 64];
    float W2[64];
    float b0[64];
    float b1[64];
    float b2v;
    float aj[3];
    float cj[3];
};

struct GroupSmem {
    float raw[192];       // dr for 64 neighbors
    float R[64];
    int   sel[NN];
    float newR[NN];
    float feat[NN * 15];
    float buf1[NN * 64];  // h1s (fwd) then gz2 (bwd)
    float buf2[NN * 64];  // gz1
    float nor[NN * 9];    // selected n_orientation
    float ndn[NN * 3];    // selected dr_norm
    float gf[NN * 15];    // g_feat
    float gdr[NN * 3];
    float gor[9];
    float red[2 * 20];
    float sArr[NN];
    float fcArr[NN];
    float gout[NN];       // q then g_out
    float O[9];
    float Fv;
    float Sv;
};

extern "C" __global__ void __launch_bounds__(256, 2)
energy_pred_kernel(const float* __restrict__ dr,
                   const float* __restrict__ orient,
                   const float* __restrict__ n_or,
                   const float* __restrict__ W0g, const float* __restrict__ b0g,
                   const float* __restrict__ W1g, const float* __restrict__ b1g,
                   const float* __restrict__ W2g, const float* __restrict__ b2g,
                   const float* __restrict__ f1g, const float* __restrict__ f2g,
                   float* __restrict__ out, int Bt)
{
    extern __shared__ char smem_raw[];
    WSmem* ws = (WSmem*)smem_raw;
    GroupSmem* gs_all = (GroupSmem*)(smem_raw + sizeof(WSmem));

    int tid = threadIdx.x;

    // ---- load weights (block cooperative) ----
    for (int i = tid; i < 15 * 64; i += 256) ws->W0[i] = W0g[i];
    for (int i = tid; i < 64 * 64; i += 256) ws->W1[i] = W1g[i];
    if (tid < 64) {
        ws->W2[tid] = W2g[tid];
        ws->b0[tid] = b0g[tid];
        ws->b1[tid] = b1g[tid];
    }
    if (tid == 0) ws->b2v = b2g[0];
    if (tid < 3) {
        float v1 = f1g[tid];
        float v2 = f2g[tid];
        ws->aj[tid] = v1 * v1 + EPSF;
        ws->cj[tid] = v2 * v2 + EPSF;
    }
    __syncthreads();

    const int g  = tid >> 6;     // group 0..3
    const int tg = tid & 63;     // thread in group
    GroupSmem* gs = &gs_all[g];
    const int b = blockIdx.x * 4 + g;
    const int barid = 1 + g;

#define GBAR() asm volatile("bar.sync %0, 64;" :: "r"(barid) : "memory")

    // ---- load dr, orientation ----
    {
        const float* drb = dr + (size_t)b * (NBK * 3);
        gs->raw[tg]       = drb[tg];
        gs->raw[tg + 64]  = drb[tg + 64];
        gs->raw[tg + 128] = drb[tg + 128];
        if (tg < 9) gs->O[tg] = orient[(size_t)b * 9 + tg];
    }
    GBAR();

    // ---- R ----
    {
        float x = gs->raw[tg * 3 + 0] + EPSF;
        float y = gs->raw[tg * 3 + 1] + EPSF;
        float z = gs->raw[tg * 3 + 2] + EPSF;
        gs->R[tg] = sqrtf(x * x + y * y + z * z);
    }
    GBAR();

    // ---- stable rank-select 20 smallest ----
    {
        float rt = gs->R[tg];
        int cnt = 0;
        #pragma unroll 8
        for (int j = 0; j < NBK; j++) {
            float rj = gs->R[j];
            cnt += (rj < rt) || (rj == rt && j < tg);
        }
        if (cnt < NN) gs->sel[cnt] = tg;
    }
    GBAR();

    // ---- gather selected n_orientation, ndn, newR ----
    {
        const float* norb = n_or + (size_t)b * (NBK * 9);
        for (int idx = tg; idx < NN * 9; idx += 64) {
            int n = idx / 9, c = idx - n * 9;
            gs->nor[idx] = norb[gs->sel[n] * 9 + c];
        }
        if (tg < 60) {
            int n = tg / 3, k = tg - n * 3;
            int s = gs->sel[n];
            gs->ndn[tg] = (gs->raw[s * 3 + k] + EPSF) / gs->R[s];
        }
        if (tg < NN) gs->newR[tg] = gs->R[gs->sel[tg]];
    }
    GBAR();

    // ---- features: [dr_o(3), dr_no(3), o_no(9)] ----
    for (int fi = tg; fi < NN * 15; fi += 64) {
        int n = fi / 15, f = fi - n * 15;
        const float* nd = &gs->ndn[n * 3];
        const float* nr = &gs->nor[n * 9];
        const float* O = gs->O;
        float v;
        if (f < 3) {
            v = nd[0] * O[f] + nd[1] * O[3 + f] + nd[2] * O[6 + f];
        } else if (f < 6) {
            int h = f - 3;
            v = nd[0] * nr[h] + nd[1] * nr[3 + h] + nd[2] * nr[6 + h];
        } else {
            int l = (f - 6) / 3, m = (f - 6) - l * 3;
            v = O[l] * nr[m] + O[3 + l] * nr[3 + m] + O[6 + l] * nr[6 + m];
        }
        gs->feat[fi] = v;
    }
    GBAR();

    // ---- layer 1: z1[n][tg], register-blocked over 20 rows ----
    float h1r[NN];
    {
        float bb = ws->b0[tg];
        #pragma unroll
        for (int n = 0; n < NN; n++) h1r[n] = bb;
        #pragma unroll 5
        for (int i = 0; i < 15; i++) {
            float w = ws->W0[i * 64 + tg];
            #pragma unroll
            for (int n = 0; n < NN; n++) h1r[n] += gs->feat[n * 15 + i] * w;
        }
        #pragma unroll
        for (int n = 0; n < NN; n++) {
            h1r[n] = tanhf(h1r[n]);
            gs->buf1[n * 64 + tg] = h1r[n];
        }
    }
    GBAR();

    // ---- layer 2 ----
    float h2r[NN];
    {
        float bb = ws->b1[tg];
        #pragma unroll
        for (int n = 0; n < NN; n++) h2r[n] = bb;
        #pragma unroll 4
        for (int k = 0; k < 64; k++) {
            float w = ws->W1[k * 64 + tg];
            #pragma unroll
            for (int n = 0; n < NN; n++) h2r[n] += gs->buf1[n * 64 + k] * w;
        }
        #pragma unroll
        for (int n = 0; n < NN; n++) h2r[n] = tanhf(h2r[n]);
    }

    // ---- output reduce: out[n] = sum_j h2[n][j]*W2[j] ----
    float w2 = ws->W2[tg];
    {
        float part[NN];
        #pragma unroll
        for (int n = 0; n < NN; n++) part[n] = h2r[n] * w2;
        #pragma unroll
        for (int off = 16; off >= 1; off >>= 1) {
            #pragma unroll
            for (int n = 0; n < NN; n++)
                part[n] += __shfl_xor_sync(0xffffffffu, part[n], off);
        }
        if ((tg & 31) == 0) {
            int w = tg >> 5;
            #pragma unroll
            for (int n = 0; n < NN; n++) gs->red[w * 20 + n] = part[n];
        }
    }
    GBAR();

    // ---- scalar tail per row (threads 0..19) ----
    if (tg < NN) {
        float outv = gs->red[tg] + gs->red[20 + tg] + ws->b2v;
        float enc = tanhf(outv);
        float ecode = enc * enc + EPSF;
        float nr = gs->newR[tg];
        float p = nr - ecode;
        float s = 0.f, dsdp = 0.f;
        #pragma unroll
        for (int j = 0; j < 3; j++) {
            float cj = ws->cj[j];
            float tj = powf(ws->aj[j] * p, -cj);
            s += tj;
            dsdp -= cj * tj / p;
        }
        gs->sArr[tg] = s;
        float fc = (nr > RCUT) ? 0.f : (0.5f * cosf(PI_F * nr / RCUT) + 0.5f);
        gs->fcArr[tg] = fc;
        gs->gout[tg] = -2.f * enc * (1.f - enc * enc) * dsdp;  // q[n]
    }
    GBAR();
    if (tg == 0) {
        float S = 0.f, F = 0.f;
        #pragma unroll
        for (int n = 0; n < NN; n++) { S += gs->sArr[n]; F += gs->fcArr[n]; }
        gs->Fv = F;
        gs->Sv = S;
    }
    GBAR();
    if (tg < NN) {
        out[(size_t)Bt * 6 + (size_t)b * NN + tg] = gs->Sv * gs->fcArr[tg];
        gs->gout[tg] *= gs->Fv;  // g_out[n]
    }
    GBAR();

    // ---- backward: gz2[n][j] = g_out[n]*W2[j]*(1-h2^2) ----
    #pragma unroll
    for (int n = 0; n < NN; n++) {
        float gv = gs->gout[n] * w2 * (1.f - h2r[n] * h2r[n]);
        gs->buf1[n * 64 + tg] = gv;
    }
    GBAR();

    // ---- g_h1[k=tg] = sum_j W1[k][j]*gz2[n][j]  (diagonal skew, conflict-free) ----
    {
        float macc[NN];
        #pragma unroll
        for (int n = 0; n < NN; n++) macc[n] = 0.f;
        #pragma unroll 4
        for (int j0 = 0; j0 < 64; j0++) {
            int jj = (j0 + tg) & 63;
            float w = ws->W1[tg * 64 + jj];
            #pragma unroll
            for (int n = 0; n < NN; n++) macc[n] += gs->buf1[n * 64 + jj] * w;
        }
        #pragma unroll
        for (int n = 0; n < NN; n++)
            gs->buf2[n * 64 + tg] = macc[n] * (1.f - h1r[n] * h1r[n]);
    }
    GBAR();

    // ---- g_feat[i][n] = sum_k W0[i][k]*gz1[n][k] ----
    if (tg < 60) {
        int n = tg % 20, ig = tg / 20;  // ig in 0..2, handles i = ig*5..ig*5+4
        float acc[5] = {0.f, 0.f, 0.f, 0.f, 0.f};
        #pragma unroll 4
        for (int k0 = 0; k0 < 64; k0++) {
            int k = (k0 + tg) & 63;
            float gz = gs->buf2[n * 64 + k];
            #pragma unroll
            for (int q = 0; q < 5; q++)
                acc[q] += ws->W0[(ig * 5 + q) * 64 + k] * gz;
        }
        #pragma unroll
        for (int q = 0; q < 5; q++) gs->gf[n * 15 + ig * 5 + q] = acc[q];
    }
    GBAR();

    // ---- g_dr and g_or accumulation ----
    if (tg < 60) {
        int n = tg % 20, k = tg / 20;  // k < 3
        const float* gf = &gs->gf[n * 15];
        const float* nr = &gs->nor[n * 9];
        float v = 0.f;
        #pragma unroll
        for (int h = 0; h < 3; h++)
            v += gf[h] * gs->O[k * 3 + h] + gf[3 + h] * nr[k * 3 + h];
        gs->gdr[n * 3 + k] = v;
    }
    if (tg < 9) {
        int r = tg / 3, c = tg - (tg / 3) * 3;
        float acc = 0.f;
        for (int n = 0; n < NN; n++) {
            const float* gf = &gs->gf[n * 15];
            const float* nr = &gs->nor[n * 9];
            acc += gf[c] * gs->ndn[n * 3 + r];
            #pragma unroll
            for (int m = 0; m < 3; m++)
                acc += gf[6 + c * 3 + m] * nr[r * 3 + m];
        }
        gs->gor[tg] = acc;
    }
    GBAR();

    // ---- force + torque ----
    if (tg < 3) {
        float f = 0.f;
        #pragma unroll
        for (int n = 0; n < NN; n++) f += gs->gdr[n * 3 + tg];
        out[(size_t)b * 3 + tg] = f;

        int i1 = (tg + 1) % 3, i2 = (tg + 2) % 3;
        float tq = 0.f;
        #pragma unroll
        for (int c = 0; c < 3; c++)
            tq += gs->gor[i1 * 3 + c] * gs->O[i2 * 3 + c]
                - gs->gor[i2 * 3 + c] * gs->O[i1 * 3 + c];
        out[(size_t)Bt * 3 + (size_t)b * 3 + tg] = tq;
    }
#undef GBAR
}

extern "C" void kernel_launch(void* const* d_in, const int* in_sizes, int n_in,
                              void* d_out, int out_size) {
    const float* dr     = (const float*)d_in[0];
    const float* orient = (const float*)d_in[1];
    const float* n_or   = (const float*)d_in[2];
    const float* W0     = (const float*)d_in[3];
    const float* b0     = (const float*)d_in[4];
    const float* W1     = (const float*)d_in[5];
    const float* b1     = (const float*)d_in[6];
    const float* W2     = (const float*)d_in[7];
    const float* b2     = (const float*)d_in[8];
    const float* f1     = (const float*)d_in[9];
    const float* f2     = (const float*)d_in[10];
    float* out = (float*)d_out;

    int B = in_sizes[0] / (64 * 3);
    size_t smem = sizeof(WSmem) + 4 * sizeof(GroupSmem);
    cudaFuncSetAttribute(energy_pred_kernel,
                         cudaFuncAttributeMaxDynamicSharedMemorySize, (int)smem);
    energy_pred_kernel<<<B / 4, 256, smem>>>(dr, orient, n_or,
                                             W0, b0, W1, b1, W2, b2, f1, f2,
                                             out, B);
}

// round 4
// speedup vs baseline: 1.1129x; 1.1129x over previous
#include <cuda_runtime.h>
#include <math.h>

#define EPSF 1e-8f
#define RCUT 4.8f
#define NBK 64
#define NN 20
#define PI_F 3.14159265358979323846f

__device__ __forceinline__ float tanh_fast(float x) {
    float e = __expf(2.f * x);
    return 1.f - __fdividef(2.f, e + 1.f);
}

struct __align__(16) WSmem {
    float W0[960];    // [15][64] forward layout
    float W0T[960];   // [64][15] backward layout
    float W1[4096];   // [64 in][64 out]
    float W1T[4096];  // [64 out][64 in]
    float W2[64];
    float b0[64];
    float b1[64];
    float aj[4];
    float cj[4];
    float b2v;
    float padw[3];
};

struct __align__(16) GroupSmem {
    float raw[192];
    float R[64];
    float newR[20];
    float featT[300];   // transposed: [15][20]
    float buf1[1280];   // transposed [64][20]: h1 (fwd), gz2 (bwd)
    float buf2[1280];   // transposed [64][20]: gz1
    float nor[180];
    float ndn[60];
    float gf[300];      // [n][15]
    float gdr[60];
    float red[40];
    float sArr[20];
    float fcArr[20];
    float gout[20];
    float gor[12];
    float O[12];
    int   sel[20];
    float Fv, Sv;
    float padg[2];
};

extern "C" __global__ void __launch_bounds__(256, 2)
energy_pred_kernel(const float* __restrict__ dr,
                   const float* __restrict__ orient,
                   const float* __restrict__ n_or,
                   const float* __restrict__ W0g, const float* __restrict__ b0g,
                   const float* __restrict__ W1g, const float* __restrict__ b1g,
                   const float* __restrict__ W2g, const float* __restrict__ b2g,
                   const float* __restrict__ f1g, const float* __restrict__ f2g,
                   float* __restrict__ out, int Bt)
{
    extern __shared__ char smem_raw[];
    WSmem* ws = (WSmem*)smem_raw;
    GroupSmem* gs_all = (GroupSmem*)(smem_raw + sizeof(WSmem));

    int tid = threadIdx.x;

    // ---- load weights (block cooperative) ----
    for (int i = tid; i < 960; i += 256) ws->W0[i] = W0g[i];
    for (int i = tid; i < 960; i += 256) {
        // W0T[k*15 + f] = W0[f*64 + k]
        int k = i / 15, f = i - k * 15;
        ws->W0T[i] = W0g[f * 64 + k];
    }
    for (int i = tid; i < 4096; i += 256) ws->W1[i] = W1g[i];
    for (int i = tid; i < 4096; i += 256) {
        // W1T[j*64 + k] = W1[k*64 + j]
        ws->W1T[i] = W1g[((i & 63) << 6) | (i >> 6)];
    }
    if (tid < 64) {
        ws->W2[tid] = W2g[tid];
        ws->b0[tid] = b0g[tid];
        ws->b1[tid] = b1g[tid];
    }
    if (tid == 0) ws->b2v = b2g[0];
    if (tid < 3) {
        float v1 = f1g[tid];
        float v2 = f2g[tid];
        ws->aj[tid] = v1 * v1 + EPSF;
        ws->cj[tid] = v2 * v2 + EPSF;
    }
    __syncthreads();

    const int g  = tid >> 6;
    const int tg = tid & 63;
    GroupSmem* gs = &gs_all[g];
    const int b = blockIdx.x * 4 + g;
    const int barid = 1 + g;

#define GBAR() asm volatile("bar.sync %0, 64;" :: "r"(barid) : "memory")

    // ---- load dr, orientation ----
    {
        const float* drb = dr + (size_t)b * (NBK * 3);
        gs->raw[tg]       = drb[tg];
        gs->raw[tg + 64]  = drb[tg + 64];
        gs->raw[tg + 128] = drb[tg + 128];
        if (tg < 9) gs->O[tg] = orient[(size_t)b * 9 + tg];
    }
    GBAR();

    // ---- R ----
    {
        float x = gs->raw[tg * 3 + 0] + EPSF;
        float y = gs->raw[tg * 3 + 1] + EPSF;
        float z = gs->raw[tg * 3 + 2] + EPSF;
        gs->R[tg] = sqrtf(x * x + y * y + z * z);
    }
    GBAR();

    // ---- stable rank-select 20 smallest ----
    {
        float rt = gs->R[tg];
        int cnt = 0;
        #pragma unroll 8
        for (int j = 0; j < NBK; j++) {
            float rj = gs->R[j];
            cnt += (rj < rt) || (rj == rt && j < tg);
        }
        if (cnt < NN) gs->sel[cnt] = tg;
    }
    GBAR();

    // ---- gather selected n_orientation, ndn, newR ----
    {
        const float* norb = n_or + (size_t)b * (NBK * 9);
        for (int idx = tg; idx < NN * 9; idx += 64) {
            int n = idx / 9, c = idx - n * 9;
            gs->nor[idx] = norb[gs->sel[n] * 9 + c];
        }
        if (tg < 60) {
            int n = tg / 3, k = tg - n * 3;
            int s = gs->sel[n];
            gs->ndn[tg] = (gs->raw[s * 3 + k] + EPSF) / gs->R[s];
        }
        if (tg < NN) gs->newR[tg] = gs->R[gs->sel[tg]];
    }
    GBAR();

    // ---- features (stored transposed: featT[f*20+n]) ----
    for (int fi = tg; fi < NN * 15; fi += 64) {
        int n = fi / 15, f = fi - n * 15;
        const float* nd = &gs->ndn[n * 3];
        const float* nr = &gs->nor[n * 9];
        const float* O = gs->O;
        float v;
        if (f < 3) {
            v = nd[0] * O[f] + nd[1] * O[3 + f] + nd[2] * O[6 + f];
        } else if (f < 6) {
            int h = f - 3;
            v = nd[0] * nr[h] + nd[1] * nr[3 + h] + nd[2] * nr[6 + h];
        } else {
            int l = (f - 6) / 3, m = (f - 6) - l * 3;
            v = O[l] * nr[m] + O[3 + l] * nr[3 + m] + O[6 + l] * nr[6 + m];
        }
        gs->featT[f * 20 + n] = v;
    }
    GBAR();

    // ---- layer 1: vectorized broadcast reads ----
    float h1r[NN];
    {
        float bb = ws->b0[tg];
        #pragma unroll
        for (int n = 0; n < NN; n++) h1r[n] = bb;
        const float4* fT = (const float4*)gs->featT;
        #pragma unroll
        for (int i = 0; i < 15; i++) {
            float w = ws->W0[i * 64 + tg];
            #pragma unroll
            for (int q = 0; q < 5; q++) {
                float4 a = fT[i * 5 + q];
                h1r[q * 4 + 0] += a.x * w;
                h1r[q * 4 + 1] += a.y * w;
                h1r[q * 4 + 2] += a.z * w;
                h1r[q * 4 + 3] += a.w * w;
            }
        }
        #pragma unroll
        for (int n = 0; n < NN; n++) h1r[n] = tanh_fast(h1r[n]);
        float4* bT = (float4*)&gs->buf1[tg * 20];
        #pragma unroll
        for (int q = 0; q < 5; q++)
            bT[q] = make_float4(h1r[q*4], h1r[q*4+1], h1r[q*4+2], h1r[q*4+3]);
    }
    GBAR();

    // ---- layer 2 ----
    float h2r[NN];
    {
        float bb = ws->b1[tg];
        #pragma unroll
        for (int n = 0; n < NN; n++) h2r[n] = bb;
        #pragma unroll 8
        for (int k = 0; k < 64; k++) {
            float w = ws->W1[k * 64 + tg];
            const float4* aT = (const float4*)&gs->buf1[k * 20];
            #pragma unroll
            for (int q = 0; q < 5; q++) {
                float4 a = aT[q];
                h2r[q * 4 + 0] += a.x * w;
                h2r[q * 4 + 1] += a.y * w;
                h2r[q * 4 + 2] += a.z * w;
                h2r[q * 4 + 3] += a.w * w;
            }
        }
        #pragma unroll
        for (int n = 0; n < NN; n++) h2r[n] = tanh_fast(h2r[n]);
    }

    // ---- output reduce ----
    float w2 = ws->W2[tg];
    {
        float part[NN];
        #pragma unroll
        for (int n = 0; n < NN; n++) part[n] = h2r[n] * w2;
        #pragma unroll
        for (int off = 16; off >= 1; off >>= 1) {
            #pragma unroll
            for (int n = 0; n < NN; n++)
                part[n] += __shfl_xor_sync(0xffffffffu, part[n], off);
        }
        if ((tg & 31) == 0) {
            int w = tg >> 5;
            #pragma unroll
            for (int n = 0; n < NN; n++) gs->red[w * 20 + n] = part[n];
        }
    }
    GBAR();

    // ---- scalar tail per row ----
    if (tg < NN) {
        float outv = gs->red[tg] + gs->red[20 + tg] + ws->b2v;
        float enc = tanh_fast(outv);
        float ecode = enc * enc + EPSF;
        float nr = gs->newR[tg];
        float p = nr - ecode;
        float s = 0.f, dsdp = 0.f;
        #pragma unroll
        for (int j = 0; j < 3; j++) {
            float cj = ws->cj[j];
            float tj = powf(ws->aj[j] * p, -cj);
            s += tj;
            dsdp -= cj * tj / p;
        }
        gs->sArr[tg] = s;
        float fc = (nr > RCUT) ? 0.f : (0.5f * cosf(PI_F * nr / RCUT) + 0.5f);
        gs->fcArr[tg] = fc;
        gs->gout[tg] = -2.f * enc * (1.f - enc * enc) * dsdp;
    }
    GBAR();
    if (tg == 0) {
        float S = 0.f, F = 0.f;
        #pragma unroll
        for (int n = 0; n < NN; n++) { S += gs->sArr[n]; F += gs->fcArr[n]; }
        gs->Fv = F;
        gs->Sv = S;
    }
    GBAR();
    if (tg < NN) {
        out[(size_t)Bt * 6 + (size_t)b * NN + tg] = gs->Sv * gs->fcArr[tg];
        gs->gout[tg] *= gs->Fv;
    }
    GBAR();

    // ---- backward: gz2 (stored transposed into buf1) ----
    {
        float go[NN];
        const float4* gp = (const float4*)gs->gout;
        #pragma unroll
        for (int q = 0; q < 5; q++) {
            float4 v = gp[q];
            go[q * 4 + 0] = v.x; go[q * 4 + 1] = v.y;
            go[q * 4 + 2] = v.z; go[q * 4 + 3] = v.w;
        }
        #pragma unroll
        for (int n = 0; n < NN; n++)
            h2r[n] = go[n] * w2 * (1.f - h2r[n] * h2r[n]);  // h2r now holds gz2
        float4* bT = (float4*)&gs->buf1[tg * 20];
        #pragma unroll
        for (int q = 0; q < 5; q++)
            bT[q] = make_float4(h2r[q*4], h2r[q*4+1], h2r[q*4+2], h2r[q*4+3]);
    }
    GBAR();

    // ---- g_h1[k=tg] via W1T, then gz1 (stored transposed into buf2) ----
    {
        float macc[NN];
        #pragma unroll
        for (int n = 0; n < NN; n++) macc[n] = 0.f;
        #pragma unroll 8
        for (int j = 0; j < 64; j++) {
            float w = ws->W1T[j * 64 + tg];
            const float4* aT = (const float4*)&gs->buf1[j * 20];
            #pragma unroll
            for (int q = 0; q < 5; q++) {
                float4 a = aT[q];
                macc[q * 4 + 0] += a.x * w;
                macc[q * 4 + 1] += a.y * w;
                macc[q * 4 + 2] += a.z * w;
                macc[q * 4 + 3] += a.w * w;
            }
        }
        #pragma unroll
        for (int n = 0; n < NN; n++)
            macc[n] *= (1.f - h1r[n] * h1r[n]);
        float4* bT = (float4*)&gs->buf2[tg * 20];
        #pragma unroll
        for (int q = 0; q < 5; q++)
            bT[q] = make_float4(macc[q*4], macc[q*4+1], macc[q*4+2], macc[q*4+3]);
    }
    GBAR();

    // ---- g_feat[n][i] = sum_k W0T[k][i] * gz1[k][n] ----
    if (tg < 60) {
        int n = tg % 20, ig = tg / 20;
        float acc[5] = {0.f, 0.f, 0.f, 0.f, 0.f};
        #pragma unroll 4
        for (int k = 0; k < 64; k++) {
            float gz = gs->buf2[k * 20 + n];
            const float* wp = &ws->W0T[k * 15 + ig * 5];
            acc[0] += wp[0] * gz;
            acc[1] += wp[1] * gz;
            acc[2] += wp[2] * gz;
            acc[3] += wp[3] * gz;
            acc[4] += wp[4] * gz;
        }
        #pragma unroll
        for (int q = 0; q < 5; q++) gs->gf[n * 15 + ig * 5 + q] = acc[q];
    }
    GBAR();

    // ---- g_dr and g_or ----
    if (tg < 60) {
        int n = tg % 20, k = tg / 20;
        const float* gf = &gs->gf[n * 15];
        const float* nr = &gs->nor[n * 9];
        float v = 0.f;
        #pragma unroll
        for (int h = 0; h < 3; h++)
            v += gf[h] * gs->O[k * 3 + h] + gf[3 + h] * nr[k * 3 + h];
        gs->gdr[n * 3 + k] = v;
    }
    if (tg < 9) {
        int r = tg / 3, c = tg - (tg / 3) * 3;
        float acc = 0.f;
        for (int n = 0; n < NN; n++) {
            const float* gf = &gs->gf[n * 15];
            const float* nr = &gs->nor[n * 9];
            acc += gf[c] * gs->ndn[n * 3 + r];
            #pragma unroll
            for (int m = 0; m < 3; m++)
                acc += gf[6 + c * 3 + m] * nr[r * 3 + m];
        }
        gs->gor[tg] = acc;
    }
    GBAR();

    // ---- force + torque ----
    if (tg < 3) {
        float f = 0.f;
        #pragma unroll
        for (int n = 0; n < NN; n++) f += gs->gdr[n * 3 + tg];
        out[(size_t)b * 3 + tg] = f;

        int i1 = (tg + 1) % 3, i2 = (tg + 2) % 3;
        float tq = 0.f;
        #pragma unroll
        for (int c = 0; c < 3; c++)
            tq += gs->gor[i1 * 3 + c] * gs->O[i2 * 3 + c]
                - gs->gor[i2 * 3 + c] * gs->O[i1 * 3 + c];
        out[(size_t)Bt * 3 + (size_t)b * 3 + tg] = tq;
    }
#undef GBAR
}

extern "C" void kernel_launch(void* const* d_in, const int* in_sizes, int n_in,
                              void* d_out, int out_size) {
    const float* dr     = (const float*)d_in[0];
    const float* orient = (const float*)d_in[1];
    const float* n_or   = (const float*)d_in[2];
    const float* W0     = (const float*)d_in[3];
    const float* b0     = (const float*)d_in[4];
    const float* W1     = (const float*)d_in[5];
    const float* b1     = (const float*)d_in[6];
    const float* W2     = (const float*)d_in[7];
    const float* b2     = (const float*)d_in[8];
    const float* f1     = (const float*)d_in[9];
    const float* f2     = (const float*)d_in[10];
    float* out = (float*)d_out;

    int B = in_sizes[0] / (64 * 3);
    size_t smem = sizeof(WSmem) + 4 * sizeof(GroupSmem);
    cudaFuncSetAttribute(energy_pred_kernel,
                         cudaFuncAttributeMaxDynamicSharedMemorySize, (int)smem);
    energy_pred_kernel<<<B / 4, 256, smem>>>(dr, orient, n_or,
                                             W0, b0, W1, b1, W2, b2, f1, f2,
                                             out, B);
}

// round 9
// speedup vs baseline: 1.6384x; 1.4722x over previous
#include <cuda_runtime.h>
#include <math.h>

#define EPSF 1e-8f
#define RCUT 4.8f
#define NBK 64
#define NN 20
#define PI_F 3.14159265358979323846f

__device__ __forceinline__ float tanh_fast(float x) {
    float e = __expf(2.f * x);
    return 1.f - __fdividef(2.f, e + 1.f);
}

struct __align__(16) WSmem {
    float2 W0p[15 * 32];   // (W0[i][t], W0[i][t+32])
    float2 W1p[64 * 32];   // (W1[k][t], W1[k][t+32])
    float2 W1Tp[64 * 32];  // (W1[t][j], W1[t+32][j]) indexed [j*32+t]
    float  W0T[64 * 16];   // W0T[k*16+i] = W0[i][k], col 15 zero-padded
    float  W2[64];
    float  b0[64];
    float  b1[64];
    float  aj[4];
    float  cj[4];
    float  b2v;
    float  padw[3];
};

struct __align__(16) GroupSmem {
    float buf1[1280];  // transposed [64][20]: h1T -> gz2T -> gz1T
    float fg[304];     // featT[f*20+n] (fwd) then gf[n*15+i] (bwd)
    float nor[180];
    float ndn[64];
    float U[256];      // raw[192]+R[64] early; red/sArr/fc/gout/gor/gdr late
    float newR[20];
    float O[12];
    int   sel[20];
    float Fv, Sv;
    float padg[2];
};

// U-region offsets (late phase)
#define U_RED  0
#define U_SARR 20
#define U_FC   40
#define U_GOUT 60
#define U_GOR  80
#define U_GDR  96

extern "C" __global__ void __launch_bounds__(256, 2)
energy_pred_kernel(const float* __restrict__ dr,
                   const float* __restrict__ orient,
                   const float* __restrict__ n_or,
                   const float* __restrict__ W0g, const float* __restrict__ b0g,
                   const float* __restrict__ W1g, const float* __restrict__ b1g,
                   const float* __restrict__ W2g, const float* __restrict__ b2g,
                   const float* __restrict__ f1g, const float* __restrict__ f2g,
                   float* __restrict__ out, int Bt)
{
    extern __shared__ char smem_raw[];
    WSmem* ws = (WSmem*)smem_raw;
    GroupSmem* gs_all = (GroupSmem*)(smem_raw + sizeof(WSmem));

    const int tid = threadIdx.x;

    // ---- weights (block cooperative, once) ----
    for (int i = tid; i < 15 * 32; i += 256) {
        int r = i >> 5, c = i & 31;
        ws->W0p[i] = make_float2(W0g[r * 64 + c], W0g[r * 64 + c + 32]);
    }
    for (int i = tid; i < 64 * 16; i += 256) {
        int k = i >> 4, f = i & 15;
        ws->W0T[i] = (f < 15) ? W0g[f * 64 + k] : 0.f;
    }
    for (int i = tid; i < 64 * 32; i += 256) {
        int k = i >> 5, c = i & 31;
        ws->W1p[i] = make_float2(W1g[k * 64 + c], W1g[k * 64 + c + 32]);
    }
    for (int i = tid; i < 64 * 32; i += 256) {
        int j = i >> 5, c = i & 31;
        ws->W1Tp[i] = make_float2(W1g[c * 64 + j], W1g[(c + 32) * 64 + j]);
    }
    if (tid < 64) {
        ws->W2[tid] = W2g[tid];
        ws->b0[tid] = b0g[tid];
        ws->b1[tid] = b1g[tid];
    }
    if (tid == 0) ws->b2v = b2g[0];
    if (tid < 3) {
        float v1 = f1g[tid];
        float v2 = f2g[tid];
        ws->aj[tid] = v1 * v1 + EPSF;
        ws->cj[tid] = v2 * v2 + EPSF;
    }
    __syncthreads();

    const int g = tid >> 5;   // group 0..7 (one warp per batch element)
    const int t = tid & 31;
    GroupSmem* gs = &gs_all[g];
    const int b = blockIdx.x * 8 + g;

    float* RAW = gs->U;        // [192]
    float* RR  = gs->U + 192;  // [64]

    // ---- load dr, orientation ----
    {
        const float* drb = dr + (size_t)b * (NBK * 3);
        #pragma unroll
        for (int i = 0; i < 6; i++) RAW[t + 32 * i] = drb[t + 32 * i];
        if (t < 9) gs->O[t] = orient[(size_t)b * 9 + t];
    }
    __syncwarp();

    // ---- R (2 rows per thread) ----
    #pragma unroll
    for (int h = 0; h < 2; h++) {
        int r = t + 32 * h;
        float x = RAW[r * 3 + 0] + EPSF;
        float y = RAW[r * 3 + 1] + EPSF;
        float z = RAW[r * 3 + 2] + EPSF;
        RR[r] = sqrtf(x * x + y * y + z * z);
    }
    __syncwarp();

    // ---- stable rank-select 20 smallest (2 rows per thread) ----
    {
        float ra = RR[t], rb = RR[t + 32];
        int ca = 0, cb = 0;
        #pragma unroll 8
        for (int j = 0; j < NBK; j++) {
            float rj = RR[j];
            ca += (rj < ra) || (rj == ra && j < t);
            cb += (rj < rb) || (rj == rb && j < t + 32);
        }
        if (ca < NN) gs->sel[ca] = t;
        if (cb < NN) gs->sel[cb] = t + 32;
    }
    __syncwarp();

    // ---- gather selected n_orientation, ndn, newR ----
    {
        const float* norb = n_or + (size_t)b * (NBK * 9);
        for (int idx = t; idx < NN * 9; idx += 32) {
            int n = idx / 9, c = idx - n * 9;
            gs->nor[idx] = norb[gs->sel[n] * 9 + c];
        }
        for (int s = t; s < 60; s += 32) {
            int n = s / 3, k = s - n * 3;
            int se = gs->sel[n];
            gs->ndn[s] = (RAW[se * 3 + k] + EPSF) / RR[se];
        }
        if (t < NN) gs->newR[t] = RR[gs->sel[t]];
    }
    __syncwarp();

    // ---- features, transposed: fg[f*20+n] ----
    for (int fi = t; fi < NN * 15; fi += 32) {
        int n = fi / 15, f = fi - n * 15;
        const float* nd = &gs->ndn[n * 3];
        const float* nr = &gs->nor[n * 9];
        const float* O = gs->O;
        float v;
        if (f < 3) {
            v = nd[0] * O[f] + nd[1] * O[3 + f] + nd[2] * O[6 + f];
        } else if (f < 6) {
            int h = f - 3;
            v = nd[0] * nr[h] + nd[1] * nr[3 + h] + nd[2] * nr[6 + h];
        } else {
            int l = (f - 6) / 3, m = (f - 6) - l * 3;
            v = O[l] * nr[m] + O[3 + l] * nr[3 + m] + O[6 + l] * nr[6 + m];
        }
        gs->fg[f * 20 + n] = v;
    }
    __syncwarp();

    // ---- layer 1: 2 output columns per thread ----
    float h1a[NN], h1b[NN];
    {
        float ba = ws->b0[t], bb = ws->b0[t + 32];
        #pragma unroll
        for (int n = 0; n < NN; n++) { h1a[n] = ba; h1b[n] = bb; }
        const float4* fT = (const float4*)gs->fg;
        #pragma unroll
        for (int i = 0; i < 15; i++) {
            float2 w = ws->W0p[i * 32 + t];
            #pragma unroll
            for (int q = 0; q < 5; q++) {
                float4 a = fT[i * 5 + q];
                h1a[q*4+0] += a.x * w.x;  h1b[q*4+0] += a.x * w.y;
                h1a[q*4+1] += a.y * w.x;  h1b[q*4+1] += a.y * w.y;
                h1a[q*4+2] += a.z * w.x;  h1b[q*4+2] += a.z * w.y;
                h1a[q*4+3] += a.w * w.x;  h1b[q*4+3] += a.w * w.y;
            }
        }
        #pragma unroll
        for (int n = 0; n < NN; n++) { h1a[n] = tanh_fast(h1a[n]); h1b[n] = tanh_fast(h1b[n]); }
        float4* sa = (float4*)&gs->buf1[t * 20];
        float4* sb = (float4*)&gs->buf1[(t + 32) * 20];
        #pragma unroll
        for (int q = 0; q < 5; q++) {
            sa[q] = make_float4(h1a[q*4], h1a[q*4+1], h1a[q*4+2], h1a[q*4+3]);
            sb[q] = make_float4(h1b[q*4], h1b[q*4+1], h1b[q*4+2], h1b[q*4+3]);
        }
    }
    __syncwarp();

    // ---- layer 2 ----
    float h2a[NN], h2b[NN];
    {
        float ba = ws->b1[t], bb = ws->b1[t + 32];
        #pragma unroll
        for (int n = 0; n < NN; n++) { h2a[n] = ba; h2b[n] = bb; }
        const float4* aT = (const float4*)gs->buf1;
        #pragma unroll 2
        for (int k = 0; k < 64; k++) {
            float2 w = ws->W1p[k * 32 + t];
            #pragma unroll
            for (int q = 0; q < 5; q++) {
                float4 a = aT[k * 5 + q];
                h2a[q*4+0] += a.x * w.x;  h2b[q*4+0] += a.x * w.y;
                h2a[q*4+1] += a.y * w.x;  h2b[q*4+1] += a.y * w.y;
                h2a[q*4+2] += a.z * w.x;  h2b[q*4+2] += a.z * w.y;
                h2a[q*4+3] += a.w * w.x;  h2b[q*4+3] += a.w * w.y;
            }
        }
        #pragma unroll
        for (int n = 0; n < NN; n++) { h2a[n] = tanh_fast(h2a[n]); h2b[n] = tanh_fast(h2b[n]); }
    }

    // ---- output reduce (warp-wide) ----
    const float w2a = ws->W2[t], w2b = ws->W2[t + 32];
    {
        float part[NN];
        #pragma unroll
        for (int n = 0; n < NN; n++) part[n] = h2a[n] * w2a + h2b[n] * w2b;
        #pragma unroll
        for (int off = 16; off >= 1; off >>= 1) {
            #pragma unroll
            for (int n = 0; n < NN; n++)
                part[n] += __shfl_xor_sync(0xffffffffu, part[n], off);
        }
        if (t == 0) {
            #pragma unroll
            for (int n = 0; n < NN; n++) gs->U[U_RED + n] = part[n];
        }
    }
    __syncwarp();

    // ---- scalar tail per row ----
    if (t < NN) {
        float outv = gs->U[U_RED + t] + ws->b2v;
        float enc = tanh_fast(outv);
        float ecode = enc * enc + EPSF;
        float nr = gs->newR[t];
        float p = nr - ecode;
        float s = 0.f, dsdp = 0.f;
        #pragma unroll
        for (int j = 0; j < 3; j++) {
            float cj = ws->cj[j];
            float tj = powf(ws->aj[j] * p, -cj);
            s += tj;
            dsdp -= cj * tj / p;
        }
        gs->U[U_SARR + t] = s;
        float fc = (nr > RCUT) ? 0.f : (0.5f * cosf(PI_F * nr / RCUT) + 0.5f);
        gs->U[U_FC + t] = fc;
        gs->U[U_GOUT + t] = -2.f * enc * (1.f - enc * enc) * dsdp;
    }
    __syncwarp();
    if (t == 0) {
        float S = 0.f, F = 0.f;
        #pragma unroll
        for (int n = 0; n < NN; n++) { S += gs->U[U_SARR + n]; F += gs->U[U_FC + n]; }
        gs->Fv = F;
        gs->Sv = S;
    }
    __syncwarp();
    if (t < NN) {
        out[(size_t)Bt * 6 + (size_t)b * NN + t] = gs->Sv * gs->U[U_FC + t];
        gs->U[U_GOUT + t] *= gs->Fv;
    }
    __syncwarp();

    // ---- gz2 (in place of h2), store transposed into buf1 ----
    {
        float go[NN];
        const float4* gp = (const float4*)(gs->U + U_GOUT);
        #pragma unroll
        for (int q = 0; q < 5; q++) {
            float4 v = gp[q];
            go[q*4+0] = v.x; go[q*4+1] = v.y; go[q*4+2] = v.z; go[q*4+3] = v.w;
        }
        #pragma unroll
        for (int n = 0; n < NN; n++) {
            h2a[n] = go[n] * w2a * (1.f - h2a[n] * h2a[n]);
            h2b[n] = go[n] * w2b * (1.f - h2b[n] * h2b[n]);
        }
        float4* sa = (float4*)&gs->buf1[t * 20];
        float4* sb = (float4*)&gs->buf1[(t + 32) * 20];
        #pragma unroll
        for (int q = 0; q < 5; q++) {
            sa[q] = make_float4(h2a[q*4], h2a[q*4+1], h2a[q*4+2], h2a[q*4+3]);
            sb[q] = make_float4(h2b[q*4], h2b[q*4+1], h2b[q*4+2], h2b[q*4+3]);
        }
    }
    __syncwarp();

    // ---- backward matvec: gh1[k=t],[k=t+32] = sum_j W1[k][j]*gz2[j][n] ----
    {
        float ma[NN], mb[NN];
        #pragma unroll
        for (int n = 0; n < NN; n++) { ma[n] = 0.f; mb[n] = 0.f; }
        const float4* aT = (const float4*)gs->buf1;
        #pragma unroll 2
        for (int j = 0; j < 64; j++) {
            float2 w = ws->W1Tp[j * 32 + t];
            #pragma unroll
            for (int q = 0; q < 5; q++) {
                float4 a = aT[j * 5 + q];
                ma[q*4+0] += a.x * w.x;  mb[q*4+0] += a.x * w.y;
                ma[q*4+1] += a.y * w.x;  mb[q*4+1] += a.y * w.y;
                ma[q*4+2] += a.z * w.x;  mb[q*4+2] += a.z * w.y;
                ma[q*4+3] += a.w * w.x;  mb[q*4+3] += a.w * w.y;
            }
        }
        #pragma unroll
        for (int n = 0; n < NN; n++) {
            ma[n] *= (1.f - h1a[n] * h1a[n]);
            mb[n] *= (1.f - h1b[n] * h1b[n]);
        }
        __syncwarp();  // everyone done reading gz2 from buf1
        float4* sa = (float4*)&gs->buf1[t * 20];
        float4* sb = (float4*)&gs->buf1[(t + 32) * 20];
        #pragma unroll
        for (int q = 0; q < 5; q++) {
            sa[q] = make_float4(ma[q*4], ma[q*4+1], ma[q*4+2], ma[q*4+3]);
            sb[q] = make_float4(mb[q*4], mb[q*4+1], mb[q*4+2], mb[q*4+3]);
        }
    }
    __syncwarp();

    // ---- g_feat: slot s=(n,ihalf), 8 i's per slot ----
    for (int s = t; s < 40; s += 32) {
        int n = s >> 1, ih = s & 1;
        int ibase = ih * 8;
        float acc[8] = {0.f, 0.f, 0.f, 0.f, 0.f, 0.f, 0.f, 0.f};
        #pragma unroll 4
        for (int k = 0; k < 64; k++) {
            float gz = gs->buf1[k * 20 + n];
            const float4* wp = (const float4*)(ws->W0T + k * 16 + ibase);
            float4 wA = wp[0], wB = wp[1];
            acc[0] += wA.x * gz; acc[1] += wA.y * gz;
            acc[2] += wA.z * gz; acc[3] += wA.w * gz;
            acc[4] += wB.x * gz; acc[5] += wB.y * gz;
            acc[6] += wB.z * gz; acc[7] += wB.w * gz;
        }
        int ni = ih ? 7 : 8;
        for (int q = 0; q < ni; q++) gs->fg[n * 15 + ibase + q] = acc[q];
    }
    __syncwarp();

    // ---- g_dr ----
    for (int s = t; s < 60; s += 32) {
        int n = s % 20, k = s / 20;
        const float* gf = &gs->fg[n * 15];
        const float* nr = &gs->nor[n * 9];
        float v = 0.f;
        #pragma unroll
        for (int h = 0; h < 3; h++)
            v += gf[h] * gs->O[k * 3 + h] + gf[3 + h] * nr[k * 3 + h];
        gs->U[U_GDR + n * 3 + k] = v;
    }
    // ---- g_or ----
    if (t < 9) {
        int r = t / 3, c = t - (t / 3) * 3;
        float acc = 0.f;
        for (int n = 0; n < NN; n++) {
            const float* gf = &gs->fg[n * 15];
            const float* nr = &gs->nor[n * 9];
            acc += gf[c] * gs->ndn[n * 3 + r];
            #pragma unroll
            for (int m = 0; m < 3; m++)
                acc += gf[6 + c * 3 + m] * nr[r * 3 + m];
        }
        gs->U[U_GOR + t] = acc;
    }
    __syncwarp();

    // ---- force + torque ----
    if (t < 3) {
        float f = 0.f;
        #pragma unroll
        for (int n = 0; n < NN; n++) f += gs->U[U_GDR + n * 3 + t];
        out[(size_t)b * 3 + t] = f;

        int i1 = (t + 1) % 3, i2 = (t + 2) % 3;
        float tq = 0.f;
        #pragma unroll
        for (int c = 0; c < 3; c++)
            tq += gs->U[U_GOR + i1 * 3 + c] * gs->O[i2 * 3 + c]
                - gs->U[U_GOR + i2 * 3 + c] * gs->O[i1 * 3 + c];
        out[(size_t)Bt * 3 + (size_t)b * 3 + t] = tq;
    }
}

extern "C" void kernel_launch(void* const* d_in, const int* in_sizes, int n_in,
                              void* d_out, int out_size) {
    const float* dr     = (const float*)d_in[0];
    const float* orient = (const float*)d_in[1];
    const float* n_or   = (const float*)d_in[2];
    const float* W0     = (const float*)d_in[3];
    const float* b0     = (const float*)d_in[4];
    const float* W1     = (const float*)d_in[5];
    const float* b1     = (const float*)d_in[6];
    const float* W2     = (const float*)d_in[7];
    const float* b2     = (const float*)d_in[8];
    const float* f1     = (const float*)d_in[9];
    const float* f2     = (const float*)d_in[10];
    float* out = (float*)d_out;

    int B = in_sizes[0] / (64 * 3);
    size_t smem = sizeof(WSmem) + 8 * sizeof(GroupSmem);
    cudaFuncSetAttribute(energy_pred_kernel,
                         cudaFuncAttributeMaxDynamicSharedMemorySize, (int)smem);
    energy_pred_kernel<<<B / 8, 256, smem>>>(dr, orient, n_or,
                                             W0, b0, W1, b1, W2, b2, f1, f2,
                                             out, B);
}

// round 14
// speedup vs baseline: 1.8054x; 1.1019x over previous
#include <cuda_runtime.h>
#include <math.h>

#define EPSF 1e-8f
#define RCUT 4.8f
#define NBK 64
#define NN 20
#define PI_F 3.14159265358979323846f

typedef unsigned long long ull;

__device__ __forceinline__ float tanh_fast(float x) {
    float e = __expf(2.f * x);
    return 1.f - __fdividef(2.f, e + 1.f);
}

__device__ __forceinline__ ull pk2(float x, float y) {
    ull r; asm("mov.b64 %0, {%1, %2};" : "=l"(r) : "f"(x), "f"(y)); return r;
}
__device__ __forceinline__ void upk2(ull v, float& x, float& y) {
    asm("mov.b64 {%0, %1}, %2;" : "=f"(x), "=f"(y) : "l"(v));
}
__device__ __forceinline__ void fma2(ull& d, ull a, ull b) {
    asm("fma.rn.f32x2 %0, %1, %2, %0;" : "+l"(d) : "l"(a), "l"(b));
}

struct __align__(16) WSmem {
    float4 W0q[15 * 16];   // (W0[i][c], [c+16], [c+32], [c+48])
    float4 W1q[64 * 16];   // (W1[k][c], ...)
    float4 W1Tq[64 * 16];  // (W1[c][j], W1[c+16][j], W1[c+32][j], W1[c+48][j]) @ [j*16+c]
    float  W0T[64 * 16];   // W0T[k*16+i] = W0[i][k], i=15 zero pad
    float4 W2q[16];
    float4 b0q[16];
    float4 b1q[16];
    float  aj[4];
    float  cj[4];
    float  b2v;
    float  padw[3];
};

struct __align__(16) GroupSmem {
    float buf1[64 * 20];  // [k][20]: h1 -> gz2 -> gz1
    float fg[304];        // featT[i*20+n] fwd; gf[n*15+i] bwd
    float nor[180];
    float ndn[64];
    float U[256];         // raw+R early; red/sArr/fc/gout/gor/gdr late
    float newR[20];
    float O[12];
    int   sel[20];
    float Fv, Sv;
    float padg[2];
};

#define U_RED  0
#define U_SARR 20
#define U_FC   40
#define U_GOUT 60
#define U_GOR  80
#define U_GDR  96

extern "C" __global__ void __launch_bounds__(256, 2)
energy_pred_kernel(const float* __restrict__ dr,
                   const float* __restrict__ orient,
                   const float* __restrict__ n_or,
                   const float* __restrict__ W0g, const float* __restrict__ b0g,
                   const float* __restrict__ W1g, const float* __restrict__ b1g,
                   const float* __restrict__ W2g, const float* __restrict__ b2g,
                   const float* __restrict__ f1g, const float* __restrict__ f2g,
                   float* __restrict__ out, int Bt)
{
    extern __shared__ char smem_raw[];
    WSmem* ws = (WSmem*)smem_raw;
    GroupSmem* gs_all = (GroupSmem*)(smem_raw + sizeof(WSmem));

    const int tid = threadIdx.x;

    // ---- weight prepack (block cooperative) ----
    for (int i = tid; i < 15 * 16; i += 256) {
        int r = i >> 4, c = i & 15;
        ws->W0q[i] = make_float4(W0g[r*64+c], W0g[r*64+c+16], W0g[r*64+c+32], W0g[r*64+c+48]);
    }
    for (int i = tid; i < 64 * 16; i += 256) {
        int k = i >> 4, c = i & 15;
        ws->W1q[i] = make_float4(W1g[k*64+c], W1g[k*64+c+16], W1g[k*64+c+32], W1g[k*64+c+48]);
    }
    for (int i = tid; i < 64 * 16; i += 256) {
        int j = i >> 4, c = i & 15;
        ws->W1Tq[i] = make_float4(W1g[c*64+j], W1g[(c+16)*64+j], W1g[(c+32)*64+j], W1g[(c+48)*64+j]);
    }
    for (int i = tid; i < 64 * 16; i += 256) {
        int k = i >> 4, f = i & 15;
        ws->W0T[i] = (f < 15) ? W0g[f * 64 + k] : 0.f;
    }
    if (tid < 16) {
        ws->W2q[tid] = make_float4(W2g[tid], W2g[tid+16], W2g[tid+32], W2g[tid+48]);
        ws->b0q[tid] = make_float4(b0g[tid], b0g[tid+16], b0g[tid+32], b0g[tid+48]);
        ws->b1q[tid] = make_float4(b1g[tid], b1g[tid+16], b1g[tid+32], b1g[tid+48]);
    }
    if (tid == 0) ws->b2v = b2g[0];
    if (tid < 3) {
        float v1 = f1g[tid], v2 = f2g[tid];
        ws->aj[tid] = v1 * v1 + EPSF;
        ws->cj[tid] = v2 * v2 + EPSF;
    }
    __syncthreads();

    const int g = tid >> 5;   // warp in block = group
    const int t = tid & 31;
    const int th = t & 15;    // column-quad index
    const int nh = t >> 4;    // n-half (0: n 0..9, 1: n 10..19)
    GroupSmem* gs = &gs_all[g];
    const int b = blockIdx.x * 8 + g;

    float* RAW = gs->U;
    float* RR  = gs->U + 192;

    // ---- load dr, orientation ----
    {
        const float* drb = dr + (size_t)b * (NBK * 3);
        #pragma unroll
        for (int i = 0; i < 6; i++) RAW[t + 32 * i] = drb[t + 32 * i];
        if (t < 9) gs->O[t] = orient[(size_t)b * 9 + t];
    }
    __syncwarp();

    #pragma unroll
    for (int h = 0; h < 2; h++) {
        int r = t + 32 * h;
        float x = RAW[r*3+0] + EPSF, y = RAW[r*3+1] + EPSF, z = RAW[r*3+2] + EPSF;
        RR[r] = sqrtf(x*x + y*y + z*z);
    }
    __syncwarp();

    // ---- stable rank-select 20 smallest ----
    {
        float ra = RR[t], rb = RR[t + 32];
        int ca = 0, cb = 0;
        #pragma unroll 8
        for (int j = 0; j < NBK; j++) {
            float rj = RR[j];
            ca += (rj < ra) || (rj == ra && j < t);
            cb += (rj < rb) || (rj == rb && j < t + 32);
        }
        if (ca < NN) gs->sel[ca] = t;
        if (cb < NN) gs->sel[cb] = t + 32;
    }
    __syncwarp();

    // ---- gather ----
    {
        const float* norb = n_or + (size_t)b * (NBK * 9);
        for (int idx = t; idx < NN * 9; idx += 32) {
            int n = idx / 9, c = idx - n * 9;
            gs->nor[idx] = norb[gs->sel[n] * 9 + c];
        }
        for (int s = t; s < 60; s += 32) {
            int n = s / 3, k = s - n * 3;
            int se = gs->sel[n];
            gs->ndn[s] = (RAW[se * 3 + k] + EPSF) / RR[se];
        }
        if (t < NN) gs->newR[t] = RR[gs->sel[t]];
    }
    __syncwarp();

    // ---- features transposed: fg[f*20+n] ----
    for (int fi = t; fi < NN * 15; fi += 32) {
        int n = fi / 15, f = fi - n * 15;
        const float* nd = &gs->ndn[n * 3];
        const float* nr = &gs->nor[n * 9];
        const float* O = gs->O;
        float v;
        if (f < 3) {
            v = nd[0]*O[f] + nd[1]*O[3+f] + nd[2]*O[6+f];
        } else if (f < 6) {
            int h = f - 3;
            v = nd[0]*nr[h] + nd[1]*nr[3+h] + nd[2]*nr[6+h];
        } else {
            int l = (f - 6) / 3, m = (f - 6) - l * 3;
            v = O[l]*nr[m] + O[3+l]*nr[3+m] + O[6+l]*nr[6+m];
        }
        gs->fg[f * 20 + n] = v;
    }
    __syncwarp();

    // ================= layer 1: 4 cols x 10 n per lane =================
    float h1f[4][10];
    {
        ull acc[4][5];
        float4 bv = ws->b0q[th];
        float bc[4] = {bv.x, bv.y, bv.z, bv.w};
        #pragma unroll
        for (int c = 0; c < 4; c++)
            #pragma unroll
            for (int p = 0; p < 5; p++) acc[c][p] = pk2(bc[c], bc[c]);
        #pragma unroll
        for (int i = 0; i < 15; i++) {
            const ull* ap = (const ull*)&gs->fg[i * 20 + nh * 10];
            ull a0 = ap[0], a1 = ap[1], a2 = ap[2], a3 = ap[3], a4 = ap[4];
            float4 w = ws->W0q[i * 16 + th];
            ull w0 = pk2(w.x, w.x), w1 = pk2(w.y, w.y), w2_ = pk2(w.z, w.z), w3 = pk2(w.w, w.w);
            fma2(acc[0][0], a0, w0); fma2(acc[0][1], a1, w0); fma2(acc[0][2], a2, w0); fma2(acc[0][3], a3, w0); fma2(acc[0][4], a4, w0);
            fma2(acc[1][0], a0, w1); fma2(acc[1][1], a1, w1); fma2(acc[1][2], a2, w1); fma2(acc[1][3], a3, w1); fma2(acc[1][4], a4, w1);
            fma2(acc[2][0], a0, w2_); fma2(acc[2][1], a1, w2_); fma2(acc[2][2], a2, w2_); fma2(acc[2][3], a3, w2_); fma2(acc[2][4], a4, w2_);
            fma2(acc[3][0], a0, w3); fma2(acc[3][1], a1, w3); fma2(acc[3][2], a2, w3); fma2(acc[3][3], a3, w3); fma2(acc[3][4], a4, w3);
        }
        #pragma unroll
        for (int c = 0; c < 4; c++)
            #pragma unroll
            for (int p = 0; p < 5; p++) {
                upk2(acc[c][p], h1f[c][2*p], h1f[c][2*p+1]);
                h1f[c][2*p]   = tanh_fast(h1f[c][2*p]);
                h1f[c][2*p+1] = tanh_fast(h1f[c][2*p+1]);
            }
        #pragma unroll
        for (int c = 0; c < 4; c++) {
            float2* dst = (float2*)&gs->buf1[(th + c*16) * 20 + nh * 10];
            #pragma unroll
            for (int p = 0; p < 5; p++) dst[p] = make_float2(h1f[c][2*p], h1f[c][2*p+1]);
        }
    }
    __syncwarp();

    // ================= layer 2 =================
    float h2f[4][10];
    {
        ull acc[4][5];
        float4 bv = ws->b1q[th];
        float bc[4] = {bv.x, bv.y, bv.z, bv.w};
        #pragma unroll
        for (int c = 0; c < 4; c++)
            #pragma unroll
            for (int p = 0; p < 5; p++) acc[c][p] = pk2(bc[c], bc[c]);
        #pragma unroll 2
        for (int k = 0; k < 64; k++) {
            const ull* ap = (const ull*)&gs->buf1[k * 20 + nh * 10];
            ull a0 = ap[0], a1 = ap[1], a2 = ap[2], a3 = ap[3], a4 = ap[4];
            float4 w = ws->W1q[k * 16 + th];
            ull w0 = pk2(w.x, w.x), w1 = pk2(w.y, w.y), w2_ = pk2(w.z, w.z), w3 = pk2(w.w, w.w);
            fma2(acc[0][0], a0, w0); fma2(acc[0][1], a1, w0); fma2(acc[0][2], a2, w0); fma2(acc[0][3], a3, w0); fma2(acc[0][4], a4, w0);
            fma2(acc[1][0], a0, w1); fma2(acc[1][1], a1, w1); fma2(acc[1][2], a2, w1); fma2(acc[1][3], a3, w1); fma2(acc[1][4], a4, w1);
            fma2(acc[2][0], a0, w2_); fma2(acc[2][1], a1, w2_); fma2(acc[2][2], a2, w2_); fma2(acc[2][3], a3, w2_); fma2(acc[2][4], a4, w2_);
            fma2(acc[3][0], a0, w3); fma2(acc[3][1], a1, w3); fma2(acc[3][2], a2, w3); fma2(acc[3][3], a3, w3); fma2(acc[3][4], a4, w3);
        }
        #pragma unroll
        for (int c = 0; c < 4; c++)
            #pragma unroll
            for (int p = 0; p < 5; p++) {
                upk2(acc[c][p], h2f[c][2*p], h2f[c][2*p+1]);
                h2f[c][2*p]   = tanh_fast(h2f[c][2*p]);
                h2f[c][2*p+1] = tanh_fast(h2f[c][2*p+1]);
            }
    }

    // ---- energy partial reduce (per n-half across 16 lanes) ----
    const float4 w2v = ws->W2q[th];
    {
        float part[10];
        #pragma unroll
        for (int n = 0; n < 10; n++)
            part[n] = h2f[0][n]*w2v.x + h2f[1][n]*w2v.y + h2f[2][n]*w2v.z + h2f[3][n]*w2v.w;
        #pragma unroll
        for (int off = 8; off >= 1; off >>= 1) {
            #pragma unroll
            for (int n = 0; n < 10; n++)
                part[n] += __shfl_xor_sync(0xffffffffu, part[n], off);
        }
        if (th == 0) {
            #pragma unroll
            for (int n = 0; n < 10; n++) gs->U[U_RED + nh * 10 + n] = part[n];
        }
    }
    __syncwarp();

    // ---- scalar tail per row ----
    if (t < NN) {
        float outv = gs->U[U_RED + t] + ws->b2v;
        float enc = tanh_fast(outv);
        float ecode = enc * enc + EPSF;
        float nr = gs->newR[t];
        float p = nr - ecode;
        float s = 0.f, dsdp = 0.f;
        #pragma unroll
        for (int j = 0; j < 3; j++) {
            float cj = ws->cj[j];
            float tj = powf(ws->aj[j] * p, -cj);
            s += tj;
            dsdp -= cj * tj / p;
        }
        gs->U[U_SARR + t] = s;
        float fc = (nr > RCUT) ? 0.f : (0.5f * cosf(PI_F * nr / RCUT) + 0.5f);
        gs->U[U_FC + t] = fc;
        gs->U[U_GOUT + t] = -2.f * enc * (1.f - enc * enc) * dsdp;
    }
    __syncwarp();
    if (t == 0) {
        float S = 0.f, F = 0.f;
        #pragma unroll
        for (int n = 0; n < NN; n++) { S += gs->U[U_SARR + n]; F += gs->U[U_FC + n]; }
        gs->Fv = F; gs->Sv = S;
    }
    __syncwarp();
    if (t < NN) {
        out[(size_t)Bt * 6 + (size_t)b * NN + t] = gs->Sv * gs->U[U_FC + t];
        gs->U[U_GOUT + t] *= gs->Fv;
    }
    __syncwarp();

    // ---- gz2: per lane 4 cols x 10 n, store to buf1 ----
    {
        float go[10];
        #pragma unroll
        for (int n = 0; n < 10; n++) go[n] = gs->U[U_GOUT + nh * 10 + n];
        float wc[4] = {w2v.x, w2v.y, w2v.z, w2v.w};
        #pragma unroll
        for (int c = 0; c < 4; c++) {
            float2* dst = (float2*)&gs->buf1[(th + c*16) * 20 + nh * 10];
            #pragma unroll
            for (int p = 0; p < 5; p++) {
                float g0 = go[2*p]   * wc[c] * (1.f - h2f[c][2*p]   * h2f[c][2*p]);
                float g1 = go[2*p+1] * wc[c] * (1.f - h2f[c][2*p+1] * h2f[c][2*p+1]);
                dst[p] = make_float2(g0, g1);
            }
        }
    }
    __syncwarp();

    // ---- backward matvec: gh1[k-quad] = sum_j W1[k][j] * gz2[j][n] ----
    {
        ull acc[4][5];
        #pragma unroll
        for (int c = 0; c < 4; c++)
            #pragma unroll
            for (int p = 0; p < 5; p++) acc[c][p] = 0ULL;
        #pragma unroll 2
        for (int j = 0; j < 64; j++) {
            const ull* ap = (const ull*)&gs->buf1[j * 20 + nh * 10];
            ull a0 = ap[0], a1 = ap[1], a2 = ap[2], a3 = ap[3], a4 = ap[4];
            float4 w = ws->W1Tq[j * 16 + th];
            ull w0 = pk2(w.x, w.x), w1 = pk2(w.y, w.y), w2_ = pk2(w.z, w.z), w3 = pk2(w.w, w.w);
            fma2(acc[0][0], a0, w0); fma2(acc[0][1], a1, w0); fma2(acc[0][2], a2, w0); fma2(acc[0][3], a3, w0); fma2(acc[0][4], a4, w0);
            fma2(acc[1][0], a0, w1); fma2(acc[1][1], a1, w1); fma2(acc[1][2], a2, w1); fma2(acc[1][3], a3, w1); fma2(acc[1][4], a4, w1);
            fma2(acc[2][0], a0, w2_); fma2(acc[2][1], a1, w2_); fma2(acc[2][2], a2, w2_); fma2(acc[2][3], a3, w2_); fma2(acc[2][4], a4, w2_);
            fma2(acc[3][0], a0, w3); fma2(acc[3][1], a1, w3); fma2(acc[3][2], a2, w3); fma2(acc[3][3], a3, w3); fma2(acc[3][4], a4, w3);
        }
        float gz1[4][10];
        #pragma unroll
        for (int c = 0; c < 4; c++)
            #pragma unroll
            for (int p = 0; p < 5; p++) {
                float x, y;
                upk2(acc[c][p], x, y);
                gz1[c][2*p]   = x * (1.f - h1f[c][2*p]   * h1f[c][2*p]);
                gz1[c][2*p+1] = y * (1.f - h1f[c][2*p+1] * h1f[c][2*p+1]);
            }
        __syncwarp();  // all gz2 reads complete before overwrite
        #pragma unroll
        for (int c = 0; c < 4; c++) {
            float2* dst = (float2*)&gs->buf1[(th + c*16) * 20 + nh * 10];
            #pragma unroll
            for (int p = 0; p < 5; p++) dst[p] = make_float2(gz1[c][2*p], gz1[c][2*p+1]);
        }
    }
    __syncwarp();

    // ---- g_feat: lanes t<10, (n-quad, i-half), FFMA2 over i-pairs ----
    if (t < 10) {
        int nq = t >> 1, ih = t & 1;
        ull acc2[4][4];
        #pragma unroll
        for (int nn = 0; nn < 4; nn++)
            #pragma unroll
            for (int ip = 0; ip < 4; ip++) acc2[nn][ip] = 0ULL;
        #pragma unroll 4
        for (int k = 0; k < 64; k++) {
            float4 gz4 = *(const float4*)&gs->buf1[k * 20 + nq * 4];
            ull g0 = pk2(gz4.x, gz4.x), g1 = pk2(gz4.y, gz4.y);
            ull g2 = pk2(gz4.z, gz4.z), g3 = pk2(gz4.w, gz4.w);
            const ull* wp = (const ull*)&ws->W0T[k * 16 + ih * 8];
            ull w0 = wp[0], w1 = wp[1], w2_ = wp[2], w3 = wp[3];
            fma2(acc2[0][0], w0, g0); fma2(acc2[0][1], w1, g0); fma2(acc2[0][2], w2_, g0); fma2(acc2[0][3], w3, g0);
            fma2(acc2[1][0], w0, g1); fma2(acc2[1][1], w1, g1); fma2(acc2[1][2], w2_, g1); fma2(acc2[1][3], w3, g1);
            fma2(acc2[2][0], w0, g2); fma2(acc2[2][1], w1, g2); fma2(acc2[2][2], w2_, g2); fma2(acc2[2][3], w3, g2);
            fma2(acc2[3][0], w0, g3); fma2(acc2[3][1], w1, g3); fma2(acc2[3][2], w2_, g3); fma2(acc2[3][3], w3, g3);
        }
        #pragma unroll
        for (int nn = 0; nn < 4; nn++) {
            int n = nq * 4 + nn;
            #pragma unroll
            for (int ip = 0; ip < 4; ip++) {
                int i = ih * 8 + 2 * ip;
                float x, y;
                upk2(acc2[nn][ip], x, y);
                gs->fg[n * 15 + i] = x;
                if (i + 1 < 15) gs->fg[n * 15 + i + 1] = y;
            }
        }
    }
    __syncwarp();

    // ---- g_dr ----
    for (int s = t; s < 60; s += 32) {
        int n = s % 20, k = s / 20;
        const float* gf = &gs->fg[n * 15];
        const float* nr = &gs->nor[n * 9];
        float v = 0.f;
        #pragma unroll
        for (int h = 0; h < 3; h++)
            v += gf[h] * gs->O[k * 3 + h] + gf[3 + h] * nr[k * 3 + h];
        gs->U[U_GDR + n * 3 + k] = v;
    }
    // ---- g_or ----
    if (t < 9) {
        int r = t / 3, c = t - (t / 3) * 3;
        float acc = 0.f;
        for (int n = 0; n < NN; n++) {
            const float* gf = &gs->fg[n * 15];
            const float* nr = &gs->nor[n * 9];
            acc += gf[c] * gs->ndn[n * 3 + r];
            #pragma unroll
            for (int m = 0; m < 3; m++)
                acc += gf[6 + c * 3 + m] * nr[r * 3 + m];
        }
        gs->U[U_GOR + t] = acc;
    }
    __syncwarp();

    // ---- force + torque ----
    if (t < 3) {
        float f = 0.f;
        #pragma unroll
        for (int n = 0; n < NN; n++) f += gs->U[U_GDR + n * 3 + t];
        out[(size_t)b * 3 + t] = f;

        int i1 = (t + 1) % 3, i2 = (t + 2) % 3;
        float tq = 0.f;
        #pragma unroll
        for (int c = 0; c < 3; c++)
            tq += gs->U[U_GOR + i1 * 3 + c] * gs->O[i2 * 3 + c]
                - gs->U[U_GOR + i2 * 3 + c] * gs->O[i1 * 3 + c];
        out[(size_t)Bt * 3 + (size_t)b * 3 + t] = tq;
    }
}

extern "C" void kernel_launch(void* const* d_in, const int* in_sizes, int n_in,
                              void* d_out, int out_size) {
    const float* dr     = (const float*)d_in[0];
    const float* orient = (const float*)d_in[1];
    const float* n_or   = (const float*)d_in[2];
    const float* W0     = (const float*)d_in[3];
    const float* b0     = (const float*)d_in[4];
    const float* W1     = (const float*)d_in[5];
    const float* b1     = (const float*)d_in[6];
    const float* W2     = (const float*)d_in[7];
    const float* b2     = (const float*)d_in[8];
    const float* f1     = (const float*)d_in[9];
    const float* f2     = (const float*)d_in[10];
    float* out = (float*)d_out;

    int B = in_sizes[0] / (64 * 3);
    size_t smem = sizeof(WSmem) + 8 * sizeof(GroupSmem);
    cudaFuncSetAttribute(energy_pred_kernel,
                         cudaFuncAttributeMaxDynamicSharedMemorySize, (int)smem);
    energy_pred_kernel<<<B / 8, 256, smem>>>(dr, orient, n_or,
                                             W0, b0, W1, b1, W2, b2, f1, f2,
                                             out, B);
}

// round 17
// speedup vs baseline: 2.0550x; 1.1382x over previous
#include <cuda_runtime.h>
#include <math.h>

#define EPSF 1e-8f
#define RCUT 4.8f
#define NBK 64
#define NN 20
#define PI_F 3.14159265358979323846f

typedef unsigned long long ull;

__device__ __forceinline__ float tanh_fast(float x) {
    float e = __expf(2.f * x);
    return 1.f - __fdividef(2.f, e + 1.f);
}

__device__ __forceinline__ ull pk2(float x, float y) {
    ull r; asm("mov.b64 %0, {%1, %2};" : "=l"(r) : "f"(x), "f"(y)); return r;
}
__device__ __forceinline__ void upk2(ull v, float& x, float& y) {
    asm("mov.b64 {%0, %1}, %2;" : "=f"(x), "=f"(y) : "l"(v));
}
__device__ __forceinline__ void fma2(ull& d, ull a, ull b) {
    asm("fma.rn.f32x2 %0, %1, %2, %0;" : "+l"(d) : "l"(a), "l"(b));
}

struct __align__(16) WSmem {
    float4 W0q[15 * 16];   // (W0[i][c], [c+16], [c+32], [c+48])
    float4 W1q[64 * 16];   // (W1[k][c], ...)
    float4 W1Tq[64 * 16];  // (W1[c][j], W1[c+16][j], W1[c+32][j], W1[c+48][j]) @ [j*16+c]
    float  W0T[64 * 16];   // W0T[k*16+i] = W0[i][k], i=15 zero pad
    float4 W2q[16];
    float4 b0q[16];
    float4 b1q[16];
    float  aj[4];
    float  cj[4];
    float  b2v;
    float  padw[3];
};

__device__ WSmem g_wpack;

struct __align__(16) GroupSmem {
    float buf1[64 * 20];  // [k][20]: h1 -> gz2 -> gz1
    float fg[304];        // featT[i*20+n] fwd; gf[n*15+i] bwd
    float nor[180];
    float ndn[64];
    float U[256];         // raw+R early; red/sArr/fc/gout/gor/gdr late
    float newR[20];
    float O[12];
    int   sel[20];
    float Fv, Sv;
    float padg[2];
};

#define U_RED  0
#define U_SARR 20
#define U_FC   40
#define U_GOUT 60
#define U_GOR  80
#define U_GDR  96

extern "C" __global__ void __launch_bounds__(256)
prepack_kernel(const float* __restrict__ W0g, const float* __restrict__ b0g,
               const float* __restrict__ W1g, const float* __restrict__ b1g,
               const float* __restrict__ W2g, const float* __restrict__ b2g,
               const float* __restrict__ f1g, const float* __restrict__ f2g)
{
    WSmem* wp = &g_wpack;
    const int tid = threadIdx.x;
    for (int i = tid; i < 15 * 16; i += 256) {
        int r = i >> 4, c = i & 15;
        wp->W0q[i] = make_float4(W0g[r*64+c], W0g[r*64+c+16], W0g[r*64+c+32], W0g[r*64+c+48]);
    }
    for (int i = tid; i < 64 * 16; i += 256) {
        int k = i >> 4, c = i & 15;
        wp->W1q[i] = make_float4(W1g[k*64+c], W1g[k*64+c+16], W1g[k*64+c+32], W1g[k*64+c+48]);
    }
    for (int i = tid; i < 64 * 16; i += 256) {
        int j = i >> 4, c = i & 15;
        wp->W1Tq[i] = make_float4(W1g[c*64+j], W1g[(c+16)*64+j], W1g[(c+32)*64+j], W1g[(c+48)*64+j]);
    }
    for (int i = tid; i < 64 * 16; i += 256) {
        int k = i >> 4, f = i & 15;
        wp->W0T[i] = (f < 15) ? W0g[f * 64 + k] : 0.f;
    }
    if (tid < 16) {
        wp->W2q[tid] = make_float4(W2g[tid], W2g[tid+16], W2g[tid+32], W2g[tid+48]);
        wp->b0q[tid] = make_float4(b0g[tid], b0g[tid+16], b0g[tid+32], b0g[tid+48]);
        wp->b1q[tid] = make_float4(b1g[tid], b1g[tid+16], b1g[tid+32], b1g[tid+48]);
    }
    if (tid == 0) { wp->b2v = b2g[0]; wp->padw[0] = 0.f; wp->padw[1] = 0.f; wp->padw[2] = 0.f; }
    if (tid < 4) {
        float v1 = (tid < 3) ? f1g[tid] : 0.f;
        float v2 = (tid < 3) ? f2g[tid] : 0.f;
        wp->aj[tid] = v1 * v1 + EPSF;
        wp->cj[tid] = v2 * v2 + EPSF;
    }
}

extern "C" __global__ void __launch_bounds__(256, 2)
energy_pred_kernel(const float* __restrict__ dr,
                   const float* __restrict__ orient,
                   const float* __restrict__ n_or,
                   float* __restrict__ out, int Bt)
{
    extern __shared__ char smem_raw[];
    WSmem* ws = (WSmem*)smem_raw;
    GroupSmem* gs_all = (GroupSmem*)(smem_raw + sizeof(WSmem));

    const int tid = threadIdx.x;

    // ---- linear copy of prepacked weights ----
    {
        constexpr int NF4 = sizeof(WSmem) / 16;
        const float4* src = (const float4*)&g_wpack;
        float4* dst = (float4*)ws;
        for (int i = tid; i < NF4; i += 256) dst[i] = src[i];
    }
    __syncthreads();

    const int g = tid >> 5;   // warp in block = group
    const int t = tid & 31;
    const int th = t & 15;    // column-quad index
    const int nh = t >> 4;    // n-half
    GroupSmem* gs = &gs_all[g];
    const int b = blockIdx.x * 8 + g;

    float* RAW = gs->U;
    float* RR  = gs->U + 192;

    // ---- load dr, orientation ----
    {
        const float* drb = dr + (size_t)b * (NBK * 3);
        #pragma unroll
        for (int i = 0; i < 6; i++) RAW[t + 32 * i] = drb[t + 32 * i];
        if (t < 9) gs->O[t] = orient[(size_t)b * 9 + t];
    }
    __syncwarp();

    #pragma unroll
    for (int h = 0; h < 2; h++) {
        int r = t + 32 * h;
        float x = RAW[r*3+0] + EPSF, y = RAW[r*3+1] + EPSF, z = RAW[r*3+2] + EPSF;
        RR[r] = sqrtf(x*x + y*y + z*z);
    }
    __syncwarp();

    // ---- stable rank-select 20 smallest ----
    {
        float ra = RR[t], rb = RR[t + 32];
        int ca = 0, cb = 0;
        #pragma unroll 8
        for (int j = 0; j < NBK; j++) {
            float rj = RR[j];
            ca += (rj < ra) || (rj == ra && j < t);
            cb += (rj < rb) || (rj == rb && j < t + 32);
        }
        if (ca < NN) gs->sel[ca] = t;
        if (cb < NN) gs->sel[cb] = t + 32;
    }
    __syncwarp();

    // ---- gather ----
    {
        const float* norb = n_or + (size_t)b * (NBK * 9);
        for (int idx = t; idx < NN * 9; idx += 32) {
            int n = idx / 9, c = idx - n * 9;
            gs->nor[idx] = norb[gs->sel[n] * 9 + c];
        }
        for (int s = t; s < 60; s += 32) {
            int n = s / 3, k = s - n * 3;
            int se = gs->sel[n];
            gs->ndn[s] = (RAW[se * 3 + k] + EPSF) / RR[se];
        }
        if (t < NN) gs->newR[t] = RR[gs->sel[t]];
    }
    __syncwarp();

    // ---- features transposed: fg[f*20+n] ----
    for (int fi = t; fi < NN * 15; fi += 32) {
        int n = fi / 15, f = fi - n * 15;
        const float* nd = &gs->ndn[n * 3];
        const float* nr = &gs->nor[n * 9];
        const float* O = gs->O;
        float v;
        if (f < 3) {
            v = nd[0]*O[f] + nd[1]*O[3+f] + nd[2]*O[6+f];
        } else if (f < 6) {
            int h = f - 3;
            v = nd[0]*nr[h] + nd[1]*nr[3+h] + nd[2]*nr[6+h];
        } else {
            int l = (f - 6) / 3, m = (f - 6) - l * 3;
            v = O[l]*nr[m] + O[3+l]*nr[3+m] + O[6+l]*nr[6+m];
        }
        gs->fg[f * 20 + n] = v;
    }
    __syncwarp();

    // ================= layer 1: 4 cols x 10 n per lane =================
    float h1f[4][10];
    {
        ull acc[4][5];
        float4 bv = ws->b0q[th];
        float bc[4] = {bv.x, bv.y, bv.z, bv.w};
        #pragma unroll
        for (int c = 0; c < 4; c++)
            #pragma unroll
            for (int p = 0; p < 5; p++) acc[c][p] = pk2(bc[c], bc[c]);
        #pragma unroll
        for (int i = 0; i < 15; i++) {
            const ull* ap = (const ull*)&gs->fg[i * 20 + nh * 10];
            ull a0 = ap[0], a1 = ap[1], a2 = ap[2], a3 = ap[3], a4 = ap[4];
            float4 w = ws->W0q[i * 16 + th];
            ull w0 = pk2(w.x, w.x), w1 = pk2(w.y, w.y), w2_ = pk2(w.z, w.z), w3 = pk2(w.w, w.w);
            fma2(acc[0][0], a0, w0); fma2(acc[0][1], a1, w0); fma2(acc[0][2], a2, w0); fma2(acc[0][3], a3, w0); fma2(acc[0][4], a4, w0);
            fma2(acc[1][0], a0, w1); fma2(acc[1][1], a1, w1); fma2(acc[1][2], a2, w1); fma2(acc[1][3], a3, w1); fma2(acc[1][4], a4, w1);
            fma2(acc[2][0], a0, w2_); fma2(acc[2][1], a1, w2_); fma2(acc[2][2], a2, w2_); fma2(acc[2][3], a3, w2_); fma2(acc[2][4], a4, w2_);
            fma2(acc[3][0], a0, w3); fma2(acc[3][1], a1, w3); fma2(acc[3][2], a2, w3); fma2(acc[3][3], a3, w3); fma2(acc[3][4], a4, w3);
        }
        #pragma unroll
        for (int c = 0; c < 4; c++)
            #pragma unroll
            for (int p = 0; p < 5; p++) {
                upk2(acc[c][p], h1f[c][2*p], h1f[c][2*p+1]);
                h1f[c][2*p]   = tanh_fast(h1f[c][2*p]);
                h1f[c][2*p+1] = tanh_fast(h1f[c][2*p+1]);
            }
        #pragma unroll
        for (int c = 0; c < 4; c++) {
            float2* dst = (float2*)&gs->buf1[(th + c*16) * 20 + nh * 10];
            #pragma unroll
            for (int p = 0; p < 5; p++) dst[p] = make_float2(h1f[c][2*p], h1f[c][2*p+1]);
        }
    }
    __syncwarp();

    // ================= layer 2 =================
    float h2f[4][10];
    {
        ull acc[4][5];
        float4 bv = ws->b1q[th];
        float bc[4] = {bv.x, bv.y, bv.z, bv.w};
        #pragma unroll
        for (int c = 0; c < 4; c++)
            #pragma unroll
            for (int p = 0; p < 5; p++) acc[c][p] = pk2(bc[c], bc[c]);
        #pragma unroll 2
        for (int k = 0; k < 64; k++) {
            const ull* ap = (const ull*)&gs->buf1[k * 20 + nh * 10];
            ull a0 = ap[0], a1 = ap[1], a2 = ap[2], a3 = ap[3], a4 = ap[4];
            float4 w = ws->W1q[k * 16 + th];
            ull w0 = pk2(w.x, w.x), w1 = pk2(w.y, w.y), w2_ = pk2(w.z, w.z), w3 = pk2(w.w, w.w);
            fma2(acc[0][0], a0, w0); fma2(acc[0][1], a1, w0); fma2(acc[0][2], a2, w0); fma2(acc[0][3], a3, w0); fma2(acc[0][4], a4, w0);
            fma2(acc[1][0], a0, w1); fma2(acc[1][1], a1, w1); fma2(acc[1][2], a2, w1); fma2(acc[1][3], a3, w1); fma2(acc[1][4], a4, w1);
            fma2(acc[2][0], a0, w2_); fma2(acc[2][1], a1, w2_); fma2(acc[2][2], a2, w2_); fma2(acc[2][3], a3, w2_); fma2(acc[2][4], a4, w2_);
            fma2(acc[3][0], a0, w3); fma2(acc[3][1], a1, w3); fma2(acc[3][2], a2, w3); fma2(acc[3][3], a3, w3); fma2(acc[3][4], a4, w3);
        }
        #pragma unroll
        for (int c = 0; c < 4; c++)
            #pragma unroll
            for (int p = 0; p < 5; p++) {
                upk2(acc[c][p], h2f[c][2*p], h2f[c][2*p+1]);
                h2f[c][2*p]   = tanh_fast(h2f[c][2*p]);
                h2f[c][2*p+1] = tanh_fast(h2f[c][2*p+1]);
            }
    }

    // ---- energy partial reduce ----
    const float4 w2v = ws->W2q[th];
    {
        float part[10];
        #pragma unroll
        for (int n = 0; n < 10; n++)
            part[n] = h2f[0][n]*w2v.x + h2f[1][n]*w2v.y + h2f[2][n]*w2v.z + h2f[3][n]*w2v.w;
        #pragma unroll
        for (int off = 8; off >= 1; off >>= 1) {
            #pragma unroll
            for (int n = 0; n < 10; n++)
                part[n] += __shfl_xor_sync(0xffffffffu, part[n], off);
        }
        if (th == 0) {
            #pragma unroll
            for (int n = 0; n < 10; n++) gs->U[U_RED + nh * 10 + n] = part[n];
        }
    }
    __syncwarp();

    // ---- scalar tail (fast intrinsics) ----
    if (t < NN) {
        float outv = gs->U[U_RED + t] + ws->b2v;
        float enc = tanh_fast(outv);
        float ecode = enc * enc + EPSF;
        float nr = gs->newR[t];
        float p = nr - ecode;
        float s = 0.f, dsdp = 0.f;
        #pragma unroll
        for (int j = 0; j < 3; j++) {
            float cj = ws->cj[j];
            float tj = __powf(ws->aj[j] * p, -cj);
            s += tj;
            dsdp -= __fdividef(cj * tj, p);
        }
        gs->U[U_SARR + t] = s;
        float fc = (nr > RCUT) ? 0.f : (0.5f * __cosf(PI_F * nr / RCUT) + 0.5f);
        gs->U[U_FC + t] = fc;
        gs->U[U_GOUT + t] = -2.f * enc * (1.f - enc * enc) * dsdp;
    }
    __syncwarp();
    if (t == 0) {
        float S = 0.f, F = 0.f;
        #pragma unroll
        for (int n = 0; n < NN; n++) { S += gs->U[U_SARR + n]; F += gs->U[U_FC + n]; }
        gs->Fv = F; gs->Sv = S;
    }
    __syncwarp();
    if (t < NN) {
        out[(size_t)Bt * 6 + (size_t)b * NN + t] = gs->Sv * gs->U[U_FC + t];
        gs->U[U_GOUT + t] *= gs->Fv;
    }
    __syncwarp();

    // ---- gz2 ----
    {
        float go[10];
        #pragma unroll
        for (int n = 0; n < 10; n++) go[n] = gs->U[U_GOUT + nh * 10 + n];
        float wc[4] = {w2v.x, w2v.y, w2v.z, w2v.w};
        #pragma unroll
        for (int c = 0; c < 4; c++) {
            float2* dst = (float2*)&gs->buf1[(th + c*16) * 20 + nh * 10];
            #pragma unroll
            for (int p = 0; p < 5; p++) {
                float g0 = go[2*p]   * wc[c] * (1.f - h2f[c][2*p]   * h2f[c][2*p]);
                float g1 = go[2*p+1] * wc[c] * (1.f - h2f[c][2*p+1] * h2f[c][2*p+1]);
                dst[p] = make_float2(g0, g1);
            }
        }
    }
    __syncwarp();

    // ---- backward matvec ----
    {
        ull acc[4][5];
        #pragma unroll
        for (int c = 0; c < 4; c++)
            #pragma unroll
            for (int p = 0; p < 5; p++) acc[c][p] = 0ULL;
        #pragma unroll 2
        for (int j = 0; j < 64; j++) {
            const ull* ap = (const ull*)&gs->buf1[j * 20 + nh * 10];
            ull a0 = ap[0], a1 = ap[1], a2 = ap[2], a3 = ap[3], a4 = ap[4];
            float4 w = ws->W1Tq[j * 16 + th];
            ull w0 = pk2(w.x, w.x), w1 = pk2(w.y, w.y), w2_ = pk2(w.z, w.z), w3 = pk2(w.w, w.w);
            fma2(acc[0][0], a0, w0); fma2(acc[0][1], a1, w0); fma2(acc[0][2], a2, w0); fma2(acc[0][3], a3, w0); fma2(acc[0][4], a4, w0);
            fma2(acc[1][0], a0, w1); fma2(acc[1][1], a1, w1); fma2(acc[1][2], a2, w1); fma2(acc[1][3], a3, w1); fma2(acc[1][4], a4, w1);
            fma2(acc[2][0], a0, w2_); fma2(acc[2][1], a1, w2_); fma2(acc[2][2], a2, w2_); fma2(acc[2][3], a3, w2_); fma2(acc[2][4], a4, w2_);
            fma2(acc[3][0], a0, w3); fma2(acc[3][1], a1, w3); fma2(acc[3][2], a2, w3); fma2(acc[3][3], a3, w3); fma2(acc[3][4], a4, w3);
        }
        float gz1[4][10];
        #pragma unroll
        for (int c = 0; c < 4; c++)
            #pragma unroll
            for (int p = 0; p < 5; p++) {
                float x, y;
                upk2(acc[c][p], x, y);
                gz1[c][2*p]   = x * (1.f - h1f[c][2*p]   * h1f[c][2*p]);
                gz1[c][2*p+1] = y * (1.f - h1f[c][2*p+1] * h1f[c][2*p+1]);
            }
        __syncwarp();  // all gz2 reads complete before overwrite
        #pragma unroll
        for (int c = 0; c < 4; c++) {
            float2* dst = (float2*)&gs->buf1[(th + c*16) * 20 + nh * 10];
            #pragma unroll
            for (int p = 0; p < 5; p++) dst[p] = make_float2(gz1[c][2*p], gz1[c][2*p+1]);
        }
    }
    __syncwarp();

    // ---- g_feat: 20 lanes, lane = n, i-pair-major accumulators ----
    if (t < NN) {
        ull acc[8];
        #pragma unroll
        for (int ip = 0; ip < 8; ip++) acc[ip] = 0ULL;
        #pragma unroll 4
        for (int k = 0; k < 64; k++) {
            float gz = gs->buf1[k * 20 + t];
            ull gzp = pk2(gz, gz);
            const ull* wp = (const ull*)&ws->W0T[k * 16];
            fma2(acc[0], wp[0], gzp); fma2(acc[1], wp[1], gzp);
            fma2(acc[2], wp[2], gzp); fma2(acc[3], wp[3], gzp);
            fma2(acc[4], wp[4], gzp); fma2(acc[5], wp[5], gzp);
            fma2(acc[6], wp[6], gzp); fma2(acc[7], wp[7], gzp);
        }
        float* gf = &gs->fg[t * 15];
        #pragma unroll
        for (int ip = 0; ip < 8; ip++) {
            float x, y;
            upk2(acc[ip], x, y);
            gf[2*ip] = x;
            if (2*ip + 1 < 15) gf[2*ip + 1] = y;
        }
    }
    __syncwarp();

    // ---- g_dr ----
    for (int s = t; s < 60; s += 32) {
        int n = s % 20, k = s / 20;
        const float* gf = &gs->fg[n * 15];
        const float* nr = &gs->nor[n * 9];
        float v = 0.f;
        #pragma unroll
        for (int h = 0; h < 3; h++)
            v += gf[h] * gs->O[k * 3 + h] + gf[3 + h] * nr[k * 3 + h];
        gs->U[U_GDR + n * 3 + k] = v;
    }
    // ---- g_or: 18 lanes (two n-halves), shfl combine ----
    {
        float acc = 0.f;
        if (t < 18) {
            int half = t / 9, idx = t - half * 9;
            int r = idx / 3, c = idx - r * 3;
            int n0 = half * 10;
            #pragma unroll
            for (int q = 0; q < 10; q++) {
                int n = n0 + q;
                const float* gf = &gs->fg[n * 15];
                const float* nr = &gs->nor[n * 9];
                acc += gf[c] * gs->ndn[n * 3 + r];
                #pragma unroll
                for (int m = 0; m < 3; m++)
                    acc += gf[6 + c * 3 + m] * nr[r * 3 + m];
            }
        }
        float other = __shfl_down_sync(0xffffffffu, acc, 9);
        if (t < 9) gs->U[U_GOR + t] = acc + other;
    }
    __syncwarp();

    // ---- force + torque ----
    if (t < 3) {
        float f = 0.f;
        #pragma unroll
        for (int n = 0; n < NN; n++) f += gs->U[U_GDR + n * 3 + t];
        out[(size_t)b * 3 + t] = f;

        int i1 = (t + 1) % 3, i2 = (t + 2) % 3;
        float tq = 0.f;
        #pragma unroll
        for (int c = 0; c < 3; c++)
            tq += gs->U[U_GOR + i1 * 3 + c] * gs->O[i2 * 3 + c]
                - gs->U[U_GOR + i2 * 3 + c] * gs->O[i1 * 3 + c];
        out[(size_t)Bt * 3 + (size_t)b * 3 + t] = tq;
    }
}

extern "C" void kernel_launch(void* const* d_in, const int* in_sizes, int n_in,
                              void* d_out, int out_size) {
    const float* dr     = (const float*)d_in[0];
    const float* orient = (const float*)d_in[1];
    const float* n_or   = (const float*)d_in[2];
    const float* W0     = (const float*)d_in[3];
    const float* b0     = (const float*)d_in[4];
    const float* W1     = (const float*)d_in[5];
    const float* b1     = (const float*)d_in[6];
    const float* W2     = (const float*)d_in[7];
    const float* b2     = (const float*)d_in[8];
    const float* f1     = (const float*)d_in[9];
    const float* f2     = (const float*)d_in[10];
    float* out = (float*)d_out;

    int B = in_sizes[0] / (64 * 3);

    prepack_kernel<<<1, 256>>>(W0, b0, W1, b1, W2, b2, f1, f2);

    size_t smem = sizeof(WSmem) + 8 * sizeof(GroupSmem);
    cudaFuncSetAttribute(energy_pred_kernel,
                         cudaFuncAttributeMaxDynamicSharedMemorySize, (int)smem);
    energy_pred_kernel<<<B / 8, 256, smem>>>(dr, orient, n_or, out, B);
}